// round 7
// baseline (speedup 1.0000x reference)
#include <cuda_runtime.h>
#include <cuda_bf16.h>
#include <math.h>

// Problem constants
#define TQ  1024
#define BQ  64
#define IQ  256
#define HQ  512
#define H4Q 2048
#define OQ  128
#define MQ  65536  // B*T

// lstm smem layout (floats)
#define WS_FLOATS (HQ * 64)        // resident W slice: 512 k x 64 cols = 32768
#define HS_FLOATS (2 * 64 * 64)    // h dup chunks, double buffered: 8192
#define GS_PITCH  66
#define GS_FLOATS (32 * GS_PITCH)  // 2112
#define SMEM_FLOATS (WS_FLOATS + HS_FLOATS + GS_FLOATS)
#define SMEM_BYTES  (SMEM_FLOATS * 4)

// ---------------------------------------------------------------------------
// Scratch (static __device__ arrays: allocation-free per harness rules)
// ---------------------------------------------------------------------------
__device__ __align__(256) float g_xg[(size_t)2 * MQ * H4Q];          // [dir][b*T+t][4H] (1 GiB)
__device__ __align__(256) float g_y [(size_t)MQ * 2 * HQ];           // [b][t][dir*H+j]  (256 MB)
__device__ __align__(256) float g_hn[2 * 2 * HQ * BQ];               // [parity][dir][j][b]
__device__ __align__(256) float g_c [2 * BQ * HQ];                   // [dir][b][j]
__device__ __align__(256) float g_wstage[(size_t)2 * 32 * HQ * 64];  // [dir][jt][k][c] (16 MB)
__device__ unsigned g_bar_count[4];
__device__ unsigned g_bar_epoch[4];

__device__ __forceinline__ float sigmf(float x) { return 1.0f / (1.0f + __expf(-x)); }

// packed f32x2 FMA: d = a*b + d (per 32-bit half)
__device__ __forceinline__ void fma2(unsigned long long& d,
                                     unsigned long long a, unsigned long long b) {
    asm("fma.rn.f32x2 %0, %1, %2, %0;" : "+l"(d) : "l"(a), "l"(b));
}
__device__ __forceinline__ unsigned long long pack2(float x) {
    unsigned long long r;
    asm("mov.b64 %0, {%1, %1};" : "=l"(r) : "f"(x));
    return r;
}

// ---------------------------------------------------------------------------
// Init: zero state + barriers, gather W_hh into per-CTA contiguous stage:
//   g_wstage[dir][jt][k][c] = W_hh_dir[(c>>4)*H + jt*16 + (c&15)][k]
// Runs every launch (graph replays must be deterministic).
// ---------------------------------------------------------------------------
__global__ void init_kernel(const float* __restrict__ Whh_f,
                            const float* __restrict__ Whh_b) {
    int idx = blockIdx.x * blockDim.x + threadIdx.x;

    const int WS_TOTAL = 2 * 32 * HQ * 64;  // 4,194,304
    if (idx < WS_TOTAL) {
        int dir = idx >> 20;
        int rem = idx & ((1 << 20) - 1);
        int jt  = rem >> 15;
        int r2  = rem & 32767;
        int k   = r2 >> 6;
        int c   = r2 & 63;
        int gr  = (c >> 4) * HQ + jt * 16 + (c & 15);
        const float* W = dir ? Whh_b : Whh_f;
        g_wstage[idx] = W[(size_t)gr * HQ + k];
    }
    if (idx < 2 * 2 * HQ * BQ) g_hn[idx] = 0.0f;
    if (idx < 2 * BQ * HQ)     g_c[idx]  = 0.0f;
    if (idx < 4) { g_bar_count[idx] = 0u; g_bar_epoch[idx] = 0u; }
}

// ---------------------------------------------------------------------------
// C[M][N] = A[M][K] * W[N][K]^T + bias1[N] (+ bias2[N])
// 128x128 tile, 256 threads, 8x8 microtile via 32 FFMA2/kk, k-chunk 16.
// ---------------------------------------------------------------------------
__global__ __launch_bounds__(256, 2) void gemm_abt_kernel(
    const float* __restrict__ A, const float* __restrict__ W,
    const float* __restrict__ bias1, const float* __restrict__ bias2,
    float* __restrict__ C, int M, int N, int K)
{
    __shared__ float As[16][132];
    __shared__ float Bs[16][132];

    const int tid = threadIdx.x;
    const int tx  = tid & 15;
    const int ty  = tid >> 4;
    const int n0  = blockIdx.x * 128;
    const int m0  = blockIdx.y * 128;

    const int lr = tid >> 1;
    const int lc = (tid & 1) << 3;

    const float* Arow = A + (size_t)(m0 + lr) * K + lc;
    const float* Wrow = W + (size_t)(n0 + lr) * K + lc;

    unsigned long long acc[8][4];  // [m][col-pair], each = 2 packed fp32
#pragma unroll
    for (int i = 0; i < 8; i++)
#pragma unroll
        for (int j = 0; j < 4; j++) acc[i][j] = 0ull;

    float4 pa0 = *(const float4*)(Arow);
    float4 pa1 = *(const float4*)(Arow + 4);
    float4 pb0 = *(const float4*)(Wrow);
    float4 pb1 = *(const float4*)(Wrow + 4);

    for (int k0 = 0; k0 < K; k0 += 16) {
        As[lc+0][lr]=pa0.x; As[lc+1][lr]=pa0.y; As[lc+2][lr]=pa0.z; As[lc+3][lr]=pa0.w;
        As[lc+4][lr]=pa1.x; As[lc+5][lr]=pa1.y; As[lc+6][lr]=pa1.z; As[lc+7][lr]=pa1.w;
        Bs[lc+0][lr]=pb0.x; Bs[lc+1][lr]=pb0.y; Bs[lc+2][lr]=pb0.z; Bs[lc+3][lr]=pb0.w;
        Bs[lc+4][lr]=pb1.x; Bs[lc+5][lr]=pb1.y; Bs[lc+6][lr]=pb1.z; Bs[lc+7][lr]=pb1.w;
        __syncthreads();

        if (k0 + 16 < K) {
            pa0 = *(const float4*)(Arow + k0 + 16);
            pa1 = *(const float4*)(Arow + k0 + 20);
            pb0 = *(const float4*)(Wrow + k0 + 16);
            pb1 = *(const float4*)(Wrow + k0 + 20);
        }

#pragma unroll
        for (int kk = 0; kk < 16; kk++) {
            float4 x0 = *(const float4*)&As[kk][ty * 8];
            float4 x1 = *(const float4*)&As[kk][ty * 8 + 4];
            ulonglong2 b01 = *(const ulonglong2*)&Bs[kk][tx * 8];      // cols (0,1),(2,3)
            ulonglong2 b23 = *(const ulonglong2*)&Bs[kk][tx * 8 + 4];  // cols (4,5),(6,7)
            float av[8] = {x0.x, x0.y, x0.z, x0.w, x1.x, x1.y, x1.z, x1.w};
#pragma unroll
            for (int i = 0; i < 8; i++) {
                unsigned long long ai = pack2(av[i]);  // ALU pipe, parallel to FMA
                fma2(acc[i][0], ai, b01.x);
                fma2(acc[i][1], ai, b01.y);
                fma2(acc[i][2], ai, b23.x);
                fma2(acc[i][3], ai, b23.y);
            }
        }
        __syncthreads();
    }

    float bv[8];
#pragma unroll
    for (int j = 0; j < 8; j++) {
        int n = n0 + tx * 8 + j;
        float b = bias1 ? bias1[n] : 0.0f;
        if (bias2) b += bias2[n];
        bv[j] = b;
    }
#pragma unroll
    for (int i = 0; i < 8; i++) {
        float* crow = C + (size_t)(m0 + ty * 8 + i) * N + n0 + tx * 8;
        float2 v0 = *(float2*)&acc[i][0];
        float2 v1 = *(float2*)&acc[i][1];
        float2 v2 = *(float2*)&acc[i][2];
        float2 v3 = *(float2*)&acc[i][3];
        float4 o0 = make_float4(v0.x + bv[0], v0.y + bv[1], v1.x + bv[2], v1.y + bv[3]);
        float4 o1 = make_float4(v2.x + bv[4], v2.y + bv[5], v3.x + bv[6], v3.y + bv[7]);
        *(float4*)(crow)     = o0;
        *(float4*)(crow + 4) = o1;
    }
}

// ---------------------------------------------------------------------------
// Persistent LSTM: ONE kernel, all 1024 steps, both directions.
// 128 CTAs (jt 0..31, bt 0..1, dir 0..1), all co-resident (1 CTA/SM).
// CTA tile: 32 b x 64 gate-cols. Warps: 2 (b-halves of 16) x 4 (col-quarters
// of 16). Thread tile 2b x 4c -> 4 FFMA2 per k.
// W slice (128 KB) resident in smem for the whole kernel. h chunks (dup'd for
// pack-free f32x2 broadcast) double-buffered. c-state in registers.
// h double-buffered globally by step parity. 4 independent 32-CTA barriers.
// ---------------------------------------------------------------------------
__global__ __launch_bounds__(256, 1) void lstm_persistent_kernel()
{
    extern __shared__ float sm[];
    float* ws = sm;                            // [k 0..511][c 0..63]
    float* hs = sm + WS_FLOATS;                // 2 x [kk 0..63][2*b 0..63] (dup)
    float* gS = sm + WS_FLOATS + HS_FLOATS;    // [32][GS_PITCH]

    const int jt  = blockIdx.x;
    const int bt  = blockIdx.y;
    const int dir = blockIdx.z;
    const int grp = dir * 2 + bt;
    const int j0  = jt * 16;
    const int b0  = bt * 32;

    const int tid  = threadIdx.x;
    const int wid  = tid >> 5, lane = tid & 31;
    const int wx   = wid & 3,  wy   = wid >> 2;
    const int tx   = lane & 3, ty   = lane >> 2;
    const int c0   = wx * 16 + tx * 4;                // local gate col (mult 4)
    const int r0   = wy * 16 + ty * 2;                // local b (even)
    const int gr   = (c0 >> 4) * HQ + j0 + (c0 & 15); // global gate row of c0..c3

    // stage resident W slice (once)
    const float* wsrc = g_wstage + ((size_t)dir * 32 + jt) * WS_FLOATS;
    for (int i = tid * 4; i < WS_FLOATS; i += 1024)
        *(float4*)&ws[i] = *(const float4*)&wsrc[i];

    // c-state lives in registers: thread owns (bl,jl) for u = tid*2 + {0,1}
    float creg[2] = {0.0f, 0.0f};

    // h staging map: thread stages row hkr, 8 src floats at seg soff
    const int hkr  = tid >> 2;          // 0..63
    const int soff = (tid & 3) * 8;     // 0,8,16,24

    const float* xgd = g_xg + (size_t)dir * MQ * H4Q;

    __syncthreads();  // ws ready

    // prefetch xg for step 0
    int t0 = dir ? (TQ - 1) : 0;
    ulonglong2 xa = *(const ulonglong2*)(xgd + ((size_t)(b0 + r0)     * TQ + t0) * H4Q + gr);
    ulonglong2 xb = *(const ulonglong2*)(xgd + ((size_t)(b0 + r0 + 1) * TQ + t0) * H4Q + gr);

    for (int s = 0; s < TQ; s++) {
        const int t = dir ? (TQ - 1 - s) : s;
        const float* hread  = g_hn + (size_t)((s & 1) * 2 + dir) * (HQ * BQ);
        float*       hwrite = g_hn + (size_t)(((s + 1) & 1) * 2 + dir) * (HQ * BQ);

        unsigned long long acc0 = xa.x, acc1 = xa.y;   // b=r0:   cols (c0,c1),(c2,c3)
        unsigned long long acc2 = xb.x, acc3 = xb.y;   // b=r0+1

        if (s + 1 < TQ) {  // prefetch next step's xg (read-only, barrier-safe)
            int tn = dir ? (t - 1) : (t + 1);
            xa = *(const ulonglong2*)(xgd + ((size_t)(b0 + r0)     * TQ + tn) * H4Q + gr);
            xb = *(const ulonglong2*)(xgd + ((size_t)(b0 + r0 + 1) * TQ + tn) * H4Q + gr);
        }

        // stage h chunk 0 (dup on the fly)
        const float* hsrc0 = hread + (size_t)hkr * BQ + b0 + soff;
        float4 q0 = *(const float4*)(hsrc0);
        float4 q1 = *(const float4*)(hsrc0 + 4);
        {
            float* d = hs + hkr * 64 + 2 * soff;
            *(float4*)(d + 0) = make_float4(q0.x, q0.x, q0.y, q0.y);
            *(float4*)(d + 4) = make_float4(q0.z, q0.z, q0.w, q0.w);
            *(float4*)(d + 8) = make_float4(q1.x, q1.x, q1.y, q1.y);
            *(float4*)(d +12) = make_float4(q1.z, q1.z, q1.w, q1.w);
        }
        __syncthreads();

        for (int ch = 0; ch < 8; ch++) {
            if (ch < 7) {  // prefetch next h chunk
                const float* src = hread + (size_t)((ch + 1) * 64 + hkr) * BQ + b0 + soff;
                q0 = *(const float4*)(src);
                q1 = *(const float4*)(src + 4);
            }
            const float* wb = ws + ch * 4096;
            const float* hb = hs + (ch & 1) * 4096;
#pragma unroll
            for (int kk = 0; kk < 64; kk++) {
                ulonglong2 w2 = *(const ulonglong2*)(wb + kk * 64 + c0);      // 1 wf
                ulonglong2 h2 = *(const ulonglong2*)(hb + kk * 64 + 2 * r0);  // 1 wf
                fma2(acc0, h2.x, w2.x);
                fma2(acc1, h2.x, w2.y);
                fma2(acc2, h2.y, w2.x);
                fma2(acc3, h2.y, w2.y);
            }
            if (ch < 7) {
                float* d = hs + ((ch + 1) & 1) * 4096 + hkr * 64 + 2 * soff;
                *(float4*)(d + 0) = make_float4(q0.x, q0.x, q0.y, q0.y);
                *(float4*)(d + 4) = make_float4(q0.z, q0.z, q0.w, q0.w);
                *(float4*)(d + 8) = make_float4(q1.x, q1.x, q1.y, q1.y);
                *(float4*)(d +12) = make_float4(q1.z, q1.z, q1.w, q1.w);
                __syncthreads();
            }
        }

        // gates -> smem for CTA-local update (8B-aligned: rows*66 even, c0 even)
        *(unsigned long long*)&gS[(r0)     * GS_PITCH + c0]     = acc0;
        *(unsigned long long*)&gS[(r0)     * GS_PITCH + c0 + 2] = acc1;
        *(unsigned long long*)&gS[(r0 + 1) * GS_PITCH + c0]     = acc2;
        *(unsigned long long*)&gS[(r0 + 1) * GS_PITCH + c0 + 2] = acc3;
        __syncthreads();

        // LSTM update: 512 (b,j) pairs, 2 per thread. Gate order i,f,g,o.
#pragma unroll
        for (int u2 = 0; u2 < 2; u2++) {
            int u  = tid * 2 + u2;
            int bl = u >> 4;
            int jl = u & 15;
            float ig = sigmf(gS[bl * GS_PITCH + jl]);
            float fg = sigmf(gS[bl * GS_PITCH + 16 + jl]);
            float gg = tanhf(gS[bl * GS_PITCH + 32 + jl]);
            float og = sigmf(gS[bl * GS_PITCH + 48 + jl]);
            float cn = fmaf(fg, creg[u2], ig * gg);
            float hn = og * tanhf(cn);
            creg[u2] = cn;
            int b = b0 + bl;
            int j = j0 + jl;
            hwrite[(size_t)j * BQ + b] = hn;
            g_y[(size_t)(b * TQ + t) * (2 * HQ) + (size_t)dir * HQ + j] = hn;
        }

        // group barrier (skip after last step; kernel exit synchronizes).
        // tid0's __threadfence (scope gpu) emits CCTL.IVALL -> this SM's L1
        // is invalidated before the next step's h loads (cross-SM coherence).
        if (s + 1 < TQ) {
            __syncthreads();
            if (tid == 0) {
                __threadfence();
                unsigned prev = atomicAdd(&g_bar_count[grp], 1u);
                if (prev == 31u) {
                    g_bar_count[grp] = 0u;
                    __threadfence();
                    atomicExch(&g_bar_epoch[grp], (unsigned)(s + 1));
                } else {
                    while (atomicAdd(&g_bar_epoch[grp], 0u) < (unsigned)(s + 1))
                        __nanosleep(20);
                    __threadfence();
                }
            }
            __syncthreads();
        }
    }

    // final c-state to global for the tail copy
#pragma unroll
    for (int u2 = 0; u2 < 2; u2++) {
        int u  = tid * 2 + u2;
        int bl = u >> 4;
        int jl = u & 15;
        g_c[(size_t)dir * BQ * HQ + (size_t)(b0 + bl) * HQ + (j0 + jl)] = creg[u2];
    }
}

// ---------------------------------------------------------------------------
// Final h/c into d_out tail. Final h is parity 0 ((1023+1)&1 == 0), [j][b].
// ---------------------------------------------------------------------------
__global__ void final_copy_kernel(float* __restrict__ hn_out, float* __restrict__ cn_out) {
    int i = blockIdx.x * blockDim.x + threadIdx.x;
    if (i < 2 * BQ * HQ) {
        int dir = i / (BQ * HQ);
        int rem = i - dir * (BQ * HQ);
        int b = rem / HQ;
        int j = rem - b * HQ;
        hn_out[i] = g_hn[(size_t)dir * (HQ * BQ) + (size_t)j * BQ + b];
        cn_out[i] = g_c[i];
    }
}

// ---------------------------------------------------------------------------
extern "C" void kernel_launch(void* const* d_in, const int* in_sizes, int n_in,
                              void* d_out, int out_size) {
    const float* inputs = (const float*)d_in[0];
    const float* W_ih_f = (const float*)d_in[1];
    const float* W_hh_f = (const float*)d_in[2];
    const float* b_ih_f = (const float*)d_in[3];
    const float* b_hh_f = (const float*)d_in[4];
    const float* W_ih_b = (const float*)d_in[5];
    const float* W_hh_b = (const float*)d_in[6];
    const float* b_ih_b = (const float*)d_in[7];
    const float* b_hh_b = (const float*)d_in[8];
    const float* W_out  = (const float*)d_in[9];
    const float* b_out  = (const float*)d_in[10];
    float* out = (float*)d_out;

    float *p_xg = nullptr, *p_y = nullptr;
    cudaGetSymbolAddress((void**)&p_xg, g_xg);
    cudaGetSymbolAddress((void**)&p_y,  g_y);

    // opt in to 168 KB dynamic smem for the persistent kernel (host-side, capture-safe)
    cudaFuncSetAttribute(lstm_persistent_kernel,
                         cudaFuncAttributeMaxDynamicSharedMemorySize, SMEM_BYTES);

    // Node 1: init (state zero + W gather + barrier reset)
    init_kernel<<<(2 * 32 * HQ * 64 + 255) / 256, 256>>>(W_hh_f, W_hh_b);

    // Nodes 2-3: xg[dir] = inputs * W_ih^T + (b_ih + b_hh)
    dim3 g1(H4Q / 128, MQ / 128);  // (16, 512)
    gemm_abt_kernel<<<g1, 256>>>(inputs, W_ih_f, b_ih_f, b_hh_f,
                                 p_xg, MQ, H4Q, IQ);
    gemm_abt_kernel<<<g1, 256>>>(inputs, W_ih_b, b_ih_b, b_hh_b,
                                 p_xg + (size_t)MQ * H4Q, MQ, H4Q, IQ);

    // Node 4: all 1024 recurrence steps in one persistent kernel
    dim3 gs(32, 2, 2);  // 128 CTAs, all co-resident
    lstm_persistent_kernel<<<gs, 256, SMEM_BYTES>>>();

    // Node 5: out = y * W_out^T + b_out
    dim3 g3(OQ / 128, MQ / 128);  // (1, 512)
    gemm_abt_kernel<<<g3, 256>>>(p_y, W_out, b_out, nullptr,
                                 out, MQ, OQ, 2 * HQ);

    // Node 6: h_n / c_n tail (only if the output buffer includes them)
    long long need = (long long)MQ * OQ + 4LL * BQ * HQ;
    if ((long long)out_size >= need)
        final_copy_kernel<<<(2 * BQ * HQ + 255) / 256, 256>>>(
            out + (size_t)MQ * OQ,
            out + (size_t)MQ * OQ + 2 * BQ * HQ);
}

// round 9
// speedup vs baseline: 1.8724x; 1.8724x over previous
#include <cuda_runtime.h>
#include <cuda_bf16.h>
#include <math.h>

// Problem constants
#define TQ  1024
#define BQ  64
#define IQ  256
#define HQ  512
#define H4Q 2048
#define OQ  128
#define MQ  65536  // B*T

// lstm smem layout (floats)
#define WS_FLOATS (HQ * 64)       // resident W slice: [k 0..511][c 0..63] = 32768
#define HS_PITCH  36
#define HS_FLOATS (HQ * HS_PITCH) // h: [k 0..511][b_local 0..31], pitch 36 = 18432
#define GS_PITCH  68              // 68 = 4*17: odd rows stay 16B-aligned (66 was the r8 bug)
#define GS_FLOATS (32 * GS_PITCH) // 2176
#define SMEM_FLOATS (WS_FLOATS + HS_FLOATS + GS_FLOATS)
#define SMEM_BYTES  (SMEM_FLOATS * 4)   // 213,504 B

// ---------------------------------------------------------------------------
// Scratch (static __device__ arrays: allocation-free per harness rules)
// ---------------------------------------------------------------------------
__device__ __align__(256) float g_xg[(size_t)2 * MQ * H4Q];          // [dir][b*T+t][4H] (1 GiB)
__device__ __align__(256) float g_y [(size_t)MQ * 2 * HQ];           // [b][t][dir*H+j]  (256 MB)
__device__ __align__(256) float g_hn[2 * 2 * HQ * BQ];               // [parity][dir][j][b]
__device__ __align__(256) float g_c [2 * BQ * HQ];                   // [dir][b][j]
__device__ __align__(256) float g_wstage[(size_t)2 * 32 * HQ * 64];  // [dir][jt][k][c] (16 MB)
__device__ unsigned g_bar_count[4];
__device__ unsigned g_bar_epoch[4];

__device__ __forceinline__ float sigmf(float x) { return 1.0f / (1.0f + __expf(-x)); }

// ---------------------------------------------------------------------------
// Init: zero state + barriers, gather W_hh into per-CTA contiguous stage:
//   g_wstage[dir][jt][k][c] = W_hh_dir[(c>>4)*H + jt*16 + (c&15)][k]
// Runs every launch (graph replays must be deterministic).
// ---------------------------------------------------------------------------
__global__ void init_kernel(const float* __restrict__ Whh_f,
                            const float* __restrict__ Whh_b) {
    int idx = blockIdx.x * blockDim.x + threadIdx.x;

    const int WS_TOTAL = 2 * 32 * HQ * 64;  // 4,194,304
    if (idx < WS_TOTAL) {
        int dir = idx >> 20;
        int rem = idx & ((1 << 20) - 1);
        int jt  = rem >> 15;
        int r2  = rem & 32767;
        int k   = r2 >> 6;
        int c   = r2 & 63;
        int gr  = (c >> 4) * HQ + jt * 16 + (c & 15);
        const float* W = dir ? Whh_b : Whh_f;
        g_wstage[idx] = W[(size_t)gr * HQ + k];
    }
    if (idx < 2 * 2 * HQ * BQ) g_hn[idx] = 0.0f;
    if (idx < 2 * BQ * HQ)     g_c[idx]  = 0.0f;
    if (idx < 4) { g_bar_count[idx] = 0u; g_bar_epoch[idx] = 0u; }
}

// ---------------------------------------------------------------------------
// C[M][N] = A[M][K] * W[N][K]^T + bias1[N] (+ bias2[N])
// 128x128 tile, 256 threads, 8x8 microtile, k-chunk 16, register prefetch.
// (Round-6 proven version: plain scalar FFMA.)
// ---------------------------------------------------------------------------
__global__ __launch_bounds__(256, 2) void gemm_abt_kernel(
    const float* __restrict__ A, const float* __restrict__ W,
    const float* __restrict__ bias1, const float* __restrict__ bias2,
    float* __restrict__ C, int M, int N, int K)
{
    __shared__ float As[16][132];
    __shared__ float Bs[16][132];

    const int tid = threadIdx.x;
    const int tx  = tid & 15;
    const int ty  = tid >> 4;
    const int n0  = blockIdx.x * 128;
    const int m0  = blockIdx.y * 128;

    const int lr = tid >> 1;
    const int lc = (tid & 1) << 3;

    const float* Arow = A + (size_t)(m0 + lr) * K + lc;
    const float* Wrow = W + (size_t)(n0 + lr) * K + lc;

    float acc[8][8];
#pragma unroll
    for (int i = 0; i < 8; i++)
#pragma unroll
        for (int j = 0; j < 8; j++) acc[i][j] = 0.0f;

    float4 pa0 = *(const float4*)(Arow);
    float4 pa1 = *(const float4*)(Arow + 4);
    float4 pb0 = *(const float4*)(Wrow);
    float4 pb1 = *(const float4*)(Wrow + 4);

    for (int k0 = 0; k0 < K; k0 += 16) {
        As[lc+0][lr]=pa0.x; As[lc+1][lr]=pa0.y; As[lc+2][lr]=pa0.z; As[lc+3][lr]=pa0.w;
        As[lc+4][lr]=pa1.x; As[lc+5][lr]=pa1.y; As[lc+6][lr]=pa1.z; As[lc+7][lr]=pa1.w;
        Bs[lc+0][lr]=pb0.x; Bs[lc+1][lr]=pb0.y; Bs[lc+2][lr]=pb0.z; Bs[lc+3][lr]=pb0.w;
        Bs[lc+4][lr]=pb1.x; Bs[lc+5][lr]=pb1.y; Bs[lc+6][lr]=pb1.z; Bs[lc+7][lr]=pb1.w;
        __syncthreads();

        if (k0 + 16 < K) {
            pa0 = *(const float4*)(Arow + k0 + 16);
            pa1 = *(const float4*)(Arow + k0 + 20);
            pb0 = *(const float4*)(Wrow + k0 + 16);
            pb1 = *(const float4*)(Wrow + k0 + 20);
        }

#pragma unroll
        for (int kk = 0; kk < 16; kk++) {
            float4 x0 = *(const float4*)&As[kk][ty * 8];
            float4 x1 = *(const float4*)&As[kk][ty * 8 + 4];
            float4 y0 = *(const float4*)&Bs[kk][tx * 8];
            float4 y1 = *(const float4*)&Bs[kk][tx * 8 + 4];
            float av[8] = {x0.x, x0.y, x0.z, x0.w, x1.x, x1.y, x1.z, x1.w};
            float bv[8] = {y0.x, y0.y, y0.z, y0.w, y1.x, y1.y, y1.z, y1.w};
#pragma unroll
            for (int i = 0; i < 8; i++)
#pragma unroll
                for (int j = 0; j < 8; j++)
                    acc[i][j] = fmaf(av[i], bv[j], acc[i][j]);
        }
        __syncthreads();
    }

    float bv[8];
#pragma unroll
    for (int j = 0; j < 8; j++) {
        int n = n0 + tx * 8 + j;
        float b = bias1 ? bias1[n] : 0.0f;
        if (bias2) b += bias2[n];
        bv[j] = b;
    }
#pragma unroll
    for (int i = 0; i < 8; i++) {
        float* crow = C + (size_t)(m0 + ty * 8 + i) * N + n0 + tx * 8;
#pragma unroll
        for (int j = 0; j < 8; j++) crow[j] = acc[i][j] + bv[j];
    }
}

// ---------------------------------------------------------------------------
// Persistent LSTM: ONE kernel, all 1024 steps, both directions.
// 128 CTAs (jt 0..31, bt 0..1, dir 0..1), all co-resident (1 CTA/SM).
// CTA tile: 32 b x 64 gate-cols; thread tile 2b x 4c (round-6 proven inner
// loop: W LDS.128 = 2 wf, h LDS.64 broadcast = 1 wf, 8 FFMA per k).
// W slice (128 KB) resident in smem for the whole kernel; h staged ONCE per
// step into smem; c-state in registers. h double-buffered globally by step
// parity. 4 independent 32-CTA group barriers.
// ---------------------------------------------------------------------------
__global__ __launch_bounds__(256, 1) void lstm_persistent_kernel()
{
    extern __shared__ float sm[];
    float* ws = sm;                            // [k][c],       512 x 64
    float* hs = sm + WS_FLOATS;                // [k][b_local], 512 x 36 pitch
    float* gS = sm + WS_FLOATS + HS_FLOATS;    // [32][GS_PITCH]

    const int jt  = blockIdx.x;
    const int bt  = blockIdx.y;
    const int dir = blockIdx.z;
    const int grp = dir * 2 + bt;
    const int j0  = jt * 16;
    const int b0  = bt * 32;

    const int tid = threadIdx.x;
    const int tx  = tid & 15;   // col group: 4 cols at c0 = tx*4
    const int ty  = tid >> 4;   // row pair:  rows r0 = ty*2, r0+1
    const int c0  = tx * 4;
    const int r0  = ty * 2;
    const int gr  = (c0 >> 4) * HQ + j0 + (c0 & 15);  // global gate row of c0..c3

    // stage resident W slice (once per kernel)
    const float* wsrc = g_wstage + ((size_t)dir * 32 + jt) * WS_FLOATS;
    for (int i = tid * 4; i < WS_FLOATS; i += 1024)
        *(float4*)&ws[i] = *(const float4*)&wsrc[i];

    // c-state in registers: thread owns u = tid*2 + {0,1} -> (bl,jl)
    float creg[2] = {0.0f, 0.0f};

    const float* xgd = g_xg + (size_t)dir * MQ * H4Q;

    __syncthreads();  // ws ready

    // prefetch xg for step 0
    int t0 = dir ? (TQ - 1) : 0;
    float4 xa = *(const float4*)(xgd + ((size_t)(b0 + r0)     * TQ + t0) * H4Q + gr);
    float4 xb = *(const float4*)(xgd + ((size_t)(b0 + r0 + 1) * TQ + t0) * H4Q + gr);

    for (int s = 0; s < TQ; s++) {
        const int t = dir ? (TQ - 1 - s) : s;
        const float* hread  = g_hn + (size_t)((s & 1) * 2 + dir) * (HQ * BQ);
        float*       hwrite = g_hn + (size_t)(((s + 1) & 1) * 2 + dir) * (HQ * BQ);

        float acc[2][4] = {{xa.x, xa.y, xa.z, xa.w}, {xb.x, xb.y, xb.z, xb.w}};

        if (s + 1 < TQ) {  // prefetch next step's xg (read-only, barrier-safe)
            int tn = dir ? (t - 1) : (t + 1);
            xa = *(const float4*)(xgd + ((size_t)(b0 + r0)     * TQ + tn) * H4Q + gr);
            xb = *(const float4*)(xgd + ((size_t)(b0 + r0 + 1) * TQ + tn) * H4Q + gr);
        }

        // stage h: 16384 floats, 16 float4 per thread.
        // f = tid + n*256 -> k = f>>3, off = (f&7)*4  (coalesced LDG.128)
#pragma unroll
        for (int n = 0; n < 16; n++) {
            int f   = tid + n * 256;
            int k   = f >> 3;
            int off = (f & 7) << 2;
            *(float4*)&hs[k * HS_PITCH + off] =
                *(const float4*)(hread + (size_t)k * BQ + b0 + off);
        }
        __syncthreads();

        // GEMM: gates[r0..r0+1][c0..c3] += h . W
#pragma unroll 4
        for (int k = 0; k < HQ; k++) {
            float4 w = *(const float4*)&ws[k * 64 + c0];       // 2 wf
            float2 h = *(const float2*)&hs[k * HS_PITCH + r0]; // broadcast, 1 wf
            acc[0][0] = fmaf(h.x, w.x, acc[0][0]);
            acc[0][1] = fmaf(h.x, w.y, acc[0][1]);
            acc[0][2] = fmaf(h.x, w.z, acc[0][2]);
            acc[0][3] = fmaf(h.x, w.w, acc[0][3]);
            acc[1][0] = fmaf(h.y, w.x, acc[1][0]);
            acc[1][1] = fmaf(h.y, w.y, acc[1][1]);
            acc[1][2] = fmaf(h.y, w.z, acc[1][2]);
            acc[1][3] = fmaf(h.y, w.w, acc[1][3]);
        }

        // gates -> smem for CTA-local update
        __syncthreads();  // all lanes done reading hs (it is rewritten next step)
        *(float4*)&gS[(r0)     * GS_PITCH + c0] =
            make_float4(acc[0][0], acc[0][1], acc[0][2], acc[0][3]);
        *(float4*)&gS[(r0 + 1) * GS_PITCH + c0] =
            make_float4(acc[1][0], acc[1][1], acc[1][2], acc[1][3]);
        __syncthreads();

        // LSTM update: 512 (b,j) pairs, 2 per thread. Gate order i,f,g,o.
#pragma unroll
        for (int u2 = 0; u2 < 2; u2++) {
            int u  = tid * 2 + u2;
            int bl = u >> 4;
            int jl = u & 15;
            float ig = sigmf(gS[bl * GS_PITCH + jl]);
            float fg = sigmf(gS[bl * GS_PITCH + 16 + jl]);
            float gg = tanhf(gS[bl * GS_PITCH + 32 + jl]);
            float og = sigmf(gS[bl * GS_PITCH + 48 + jl]);
            float cn = fmaf(fg, creg[u2], ig * gg);
            float hn = og * tanhf(cn);
            creg[u2] = cn;
            int b = b0 + bl;
            int j = j0 + jl;
            hwrite[(size_t)j * BQ + b] = hn;
            g_y[(size_t)(b * TQ + t) * (2 * HQ) + (size_t)dir * HQ + j] = hn;
        }

        // group barrier (skip after last step; kernel exit synchronizes)
        if (s + 1 < TQ) {
            __syncthreads();
            if (tid == 0) {
                __threadfence();
                unsigned prev = atomicAdd(&g_bar_count[grp], 1u);
                if (prev == 31u) {
                    g_bar_count[grp] = 0u;
                    __threadfence();
                    atomicExch(&g_bar_epoch[grp], (unsigned)(s + 1));
                } else {
                    while (atomicAdd(&g_bar_epoch[grp], 0u) < (unsigned)(s + 1))
                        __nanosleep(20);
                    __threadfence();
                }
            }
            __syncthreads();
        }
    }

    // final c-state to global for the tail copy
#pragma unroll
    for (int u2 = 0; u2 < 2; u2++) {
        int u  = tid * 2 + u2;
        int bl = u >> 4;
        int jl = u & 15;
        g_c[(size_t)dir * BQ * HQ + (size_t)(b0 + bl) * HQ + (j0 + jl)] = creg[u2];
    }
}

// ---------------------------------------------------------------------------
// Final h/c into d_out tail. Final h is parity 0 ((1023+1)&1 == 0), [j][b].
// ---------------------------------------------------------------------------
__global__ void final_copy_kernel(float* __restrict__ hn_out, float* __restrict__ cn_out) {
    int i = blockIdx.x * blockDim.x + threadIdx.x;
    if (i < 2 * BQ * HQ) {
        int dir = i / (BQ * HQ);
        int rem = i - dir * (BQ * HQ);
        int b = rem / HQ;
        int j = rem - b * HQ;
        hn_out[i] = g_hn[(size_t)dir * (HQ * BQ) + (size_t)j * BQ + b];
        cn_out[i] = g_c[i];
    }
}

// ---------------------------------------------------------------------------
extern "C" void kernel_launch(void* const* d_in, const int* in_sizes, int n_in,
                              void* d_out, int out_size) {
    const float* inputs = (const float*)d_in[0];
    const float* W_ih_f = (const float*)d_in[1];
    const float* W_hh_f = (const float*)d_in[2];
    const float* b_ih_f = (const float*)d_in[3];
    const float* b_hh_f = (const float*)d_in[4];
    const float* W_ih_b = (const float*)d_in[5];
    const float* W_hh_b = (const float*)d_in[6];
    const float* b_ih_b = (const float*)d_in[7];
    const float* b_hh_b = (const float*)d_in[8];
    const float* W_out  = (const float*)d_in[9];
    const float* b_out  = (const float*)d_in[10];
    float* out = (float*)d_out;

    float *p_xg = nullptr, *p_y = nullptr;
    cudaGetSymbolAddress((void**)&p_xg, g_xg);
    cudaGetSymbolAddress((void**)&p_y,  g_y);

    // opt in to 208+ KB dynamic smem for the persistent kernel
    cudaFuncSetAttribute(lstm_persistent_kernel,
                         cudaFuncAttributeMaxDynamicSharedMemorySize, SMEM_BYTES);

    // Node 1: init (state zero + W gather + barrier reset)
    init_kernel<<<(2 * 32 * HQ * 64 + 255) / 256, 256>>>(W_hh_f, W_hh_b);

    // Nodes 2-3: xg[dir] = inputs * W_ih^T + (b_ih + b_hh)
    dim3 g1(H4Q / 128, MQ / 128);  // (16, 512)
    gemm_abt_kernel<<<g1, 256>>>(inputs, W_ih_f, b_ih_f, b_hh_f,
                                 p_xg, MQ, H4Q, IQ);
    gemm_abt_kernel<<<g1, 256>>>(inputs, W_ih_b, b_ih_b, b_hh_b,
                                 p_xg + (size_t)MQ * H4Q, MQ, H4Q, IQ);

    // Node 4: all 1024 recurrence steps in one persistent kernel
    dim3 gs(32, 2, 2);  // 128 CTAs, all co-resident
    lstm_persistent_kernel<<<gs, 256, SMEM_BYTES>>>();

    // Node 5: out = y * W_out^T + b_out
    dim3 g3(OQ / 128, MQ / 128);  // (1, 512)
    gemm_abt_kernel<<<g3, 256>>>(p_y, W_out, b_out, nullptr,
                                 out, MQ, OQ, 2 * HQ);

    // Node 6: h_n / c_n tail (only if the output buffer includes them)
    long long need = (long long)MQ * OQ + 4LL * BQ * HQ;
    if ((long long)out_size >= need)
        final_copy_kernel<<<(2 * BQ * HQ + 255) / 256, 256>>>(
            out + (size_t)MQ * OQ,
            out + (size_t)MQ * OQ + 2 * BQ * HQ);
}